// round 2
// baseline (speedup 1.0000x reference)
#include <cuda_runtime.h>
#include <math.h>

// Per-point record: 5 float4 (20 floats), coefficients DUPLICATED so that
// LDS.128 lands packed-splat f32x2 operands in adjacent registers:
//   v0 = (nb, nb, nc, nc)
//   v1 = (nE, nE, na, na)
//   v2 = (nD, nD, F1, F1)
//   v3 = (wr, wr, wg, wg)
//   v4 = (wb, wb,  0,  0)
// where  d = a*y^2 + b*x^2 + c*x*y + D*y + E*x + F  and  m = max(1-d, 0):
//   nb=-b, nc=-c, nE=-E, na=-a, nD=-D, F1=1-F,  w* = color*alpha
#define MAXP 4096
__device__ float4 g_pdata[MAXP * 5];

typedef unsigned long long u64;

__device__ __forceinline__ u64 ffma2(u64 a, u64 b, u64 c) {
    u64 d;
    asm("fma.rn.f32x2 %0, %1, %2, %3;" : "=l"(d) : "l"(a), "l"(b), "l"(c));
    return d;
}
__device__ __forceinline__ u64 pack2(float lo, float hi) {
    u64 d;
    asm("mov.b64 %0, {%1, %2};" : "=l"(d) : "f"(lo), "f"(hi));
    return d;
}
__device__ __forceinline__ float2 unpack2(u64 a) {
    float2 r;
    asm("mov.b64 {%0, %1}, %2;" : "=f"(r.x), "=f"(r.y) : "l"(a));
    return r;
}

__global__ void prep_kernel(const float* __restrict__ loc,
                            const float* __restrict__ moff,
                            const float* __restrict__ msfo,
                            const float* __restrict__ colors,
                            const float* __restrict__ alphas,
                            int P)
{
    int p = blockIdx.x * blockDim.x + threadIdx.x;
    if (p >= P) return;

    float scale = 0.5f * sqrtf((float)P) * expf(msfo[p]);
    float T00 = moff[p * 4 + 0] + scale;
    float T01 = moff[p * 4 + 1];
    float T10 = moff[p * 4 + 2];
    float T11 = moff[p * 4 + 3] + scale;

    float a = T00 * T00 + T01 * T01;
    float b = T10 * T10 + T11 * T11;
    float c = 2.0f * (T00 * T10 + T01 * T11);

    float ly = loc[p * 2 + 0];
    float lx = loc[p * 2 + 1];

    float D = -(2.0f * a * ly + c * lx);
    float E = -(2.0f * b * lx + c * ly);
    float F = a * ly * ly + b * lx * lx + c * lx * ly;

    float al = alphas[p];
    float wr = colors[p * 3 + 0] * al;
    float wg = colors[p * 3 + 1] * al;
    float wb = colors[p * 3 + 2] * al;

    float4* q = g_pdata + p * 5;
    q[0] = make_float4(-b, -b, -c, -c);
    q[1] = make_float4(-E, -E, -a, -a);
    q[2] = make_float4(-D, -D, 1.0f - F, 1.0f - F);
    q[3] = make_float4(wr, wr, wg, wg);
    q[4] = make_float4(wb, wb, 0.0f, 0.0f);
}

#define TPB   64      // threads per block; one block == one canvas row
#define NPAIR 4       // pixel PAIRS per thread -> 8 pixels/thread

__global__ __launch_bounds__(TPB)
void render_kernel(float* __restrict__ out, int H, int W, int P, float ratio)
{
    extern __shared__ float4 s4[];   // 5 * P float4

    const int nrec = 5 * P;
    for (int i = threadIdx.x; i < nrec; i += TPB) s4[i] = g_pdata[i];
    __syncthreads();

    const int row = blockIdx.x;
    const float y = -1.0f + (float)row * (2.0f / (float)(H - 1));
    const u64 y2 = pack2(y, y);

    const float dx = 2.0f * ratio / (float)(W - 1);

    u64 x2[NPAIR];
#pragma unroll
    for (int k = 0; k < NPAIR; k++) {
        int px = (threadIdx.x + k * TPB) * 2;
        x2[k] = pack2(-ratio + (float)px * dx, -ratio + (float)(px + 1) * dx);
    }

    u64 ar[NPAIR], ag[NPAIR], ab[NPAIR];
    const u64 z2 = pack2(0.0f, 0.0f);
#pragma unroll
    for (int k = 0; k < NPAIR; k++) { ar[k] = z2; ag[k] = z2; ab[k] = z2; }

#pragma unroll 2
    for (int p = 0; p < P; p++) {
        const float4 v0 = s4[p * 5 + 0];
        const float4 v1 = s4[p * 5 + 1];
        const float4 v2 = s4[p * 5 + 2];
        const float4 v3 = s4[p * 5 + 3];
        const float4 v4 = s4[p * 5 + 4];

        const u64 nb2 = pack2(v0.x, v0.y);
        const u64 nc2 = pack2(v0.z, v0.w);
        const u64 nE2 = pack2(v1.x, v1.y);
        const u64 na2 = pack2(v1.z, v1.w);
        const u64 nD2 = pack2(v2.x, v2.y);
        const u64 F12 = pack2(v2.z, v2.w);
        const u64 wr2 = pack2(v3.x, v3.y);
        const u64 wg2 = pack2(v3.z, v3.w);
        const u64 wb2 = pack2(v4.x, v4.y);

        // per-(point,row) terms, packed, amortized over NPAIR pairs
        const u64 ng2 = ffma2(y2, nc2, nE2);
        const u64 h12 = ffma2(y2, ffma2(y2, na2, nD2), F12);

#pragma unroll
        for (int k = 0; k < NPAIR; k++) {
            u64 t = ffma2(x2[k], nb2, ng2);
            u64 w = ffma2(x2[k], t, h12);
            float2 wf = unpack2(w);
            u64 m = pack2(fmaxf(wf.x, 0.0f), fmaxf(wf.y, 0.0f));
            ar[k] = ffma2(m, wr2, ar[k]);
            ag[k] = ffma2(m, wg2, ag[k]);
            ab[k] = ffma2(m, wb2, ab[k]);
        }
    }

    // sigmoid(4*canvas) epilogue + store (2 pixels = 6 contiguous floats)
#pragma unroll
    for (int k = 0; k < NPAIR; k++) {
        int pi = threadIdx.x + k * TPB;
        int px = pi * 2;
        if (px + 1 < W) {
            float2 r = unpack2(ar[k]);
            float2 g = unpack2(ag[k]);
            float2 b = unpack2(ab[k]);
            float* o = out + ((size_t)row * W + px) * 3;
            o[0] = 1.0f / (1.0f + __expf(-4.0f * r.x));
            o[1] = 1.0f / (1.0f + __expf(-4.0f * g.x));
            o[2] = 1.0f / (1.0f + __expf(-4.0f * b.x));
            o[3] = 1.0f / (1.0f + __expf(-4.0f * r.y));
            o[4] = 1.0f / (1.0f + __expf(-4.0f * g.y));
            o[5] = 1.0f / (1.0f + __expf(-4.0f * b.y));
        }
    }
}

extern "C" void kernel_launch(void* const* d_in, const int* in_sizes, int n_in,
                              void* d_out, int out_size)
{
    const float* loc    = (const float*)d_in[2];
    const float* moff   = (const float*)d_in[3];
    const float* msfo   = (const float*)d_in[4];
    const float* colors = (const float*)d_in[5];
    const float* alphas = (const float*)d_in[6];
    float* out = (float*)d_out;

    int P = in_sizes[2] / 2;             // locations has P*2 elements
    int HW = out_size / 3;               // output is H*W*3
    int H = (int)(sqrt((double)HW) + 0.5);
    int W = HW / H;
    float ratio = (float)W / (float)H;

    prep_kernel<<<(P + 127) / 128, 128>>>(loc, moff, msfo, colors, alphas, P);

    size_t smem = (size_t)(5 * P) * sizeof(float4);   // 40 KB for P=512
    render_kernel<<<H, TPB, smem>>>(out, H, W, P, ratio);
}

// round 3
// speedup vs baseline: 2.3080x; 2.3080x over previous
#include <cuda_runtime.h>
#include <math.h>

typedef unsigned long long u64;

__device__ __forceinline__ u64 ffma2(u64 a, u64 b, u64 c) {
    u64 d;
    asm("fma.rn.f32x2 %0, %1, %2, %3;" : "=l"(d) : "l"(a), "l"(b), "l"(c));
    return d;
}
__device__ __forceinline__ u64 pack2(float lo, float hi) {
    u64 d;
    asm("mov.b64 %0, {%1, %2};" : "=l"(d) : "f"(lo), "f"(hi));
    return d;
}
__device__ __forceinline__ float2 unpack2(u64 a) {
    float2 r;
    asm("mov.b64 {%0, %1}, %2;" : "=f"(r.x), "=f"(r.y) : "l"(a));
    return r;
}

// d(x,y) = a*y^2 + b*x^2 + c*x*y + D*y + E*x + F ; m = max(1-d, 0)
// per-point:  nb=-b, nc=-c, nE=-E, na=-a, nD=-D, F1=1-F, w*=color*alpha
// per-(row,point):  ng = nc*y + nE,  h1 = (na*y + nD)*y + F1
// row max of (nb x^2 + ng x + h1) = h1 - ng^2/(4 nb)  (nb < 0)
#define MAXP   2048
#define MAXH   1024
#define ROWCAP 1024   // >= P for this problem family

// Kernel A output: 3 float4 per point
//   q0 = (nb, nc, nE, na)   q1 = (nD, F1, wr, wg)   q2 = (wb, 0, 0, 0)
__device__ float4 g_pdata[MAXP * 3];
// Kernel B output: 3 float4 per active (row, point), duplicated for f32x2:
//   r0 = (nb,nb,ng,ng)  r1 = (h1,h1,wr,wr)  r2 = (wg,wg,wb,wb)
__device__ float4 g_rowlist[(size_t)MAXH * ROWCAP * 3];
__device__ int    g_rowcount[MAXH];

__global__ void prep_kernel(const float* __restrict__ loc,
                            const float* __restrict__ moff,
                            const float* __restrict__ msfo,
                            const float* __restrict__ colors,
                            const float* __restrict__ alphas,
                            int P)
{
    int p = blockIdx.x * blockDim.x + threadIdx.x;
    if (p >= P) return;

    float scale = 0.5f * sqrtf((float)P) * expf(msfo[p]);
    float T00 = moff[p * 4 + 0] + scale;
    float T01 = moff[p * 4 + 1];
    float T10 = moff[p * 4 + 2];
    float T11 = moff[p * 4 + 3] + scale;

    float a = T00 * T00 + T01 * T01;
    float b = T10 * T10 + T11 * T11;
    float c = 2.0f * (T00 * T10 + T01 * T11);

    float ly = loc[p * 2 + 0];
    float lx = loc[p * 2 + 1];

    float D = -(2.0f * a * ly + c * lx);
    float E = -(2.0f * b * lx + c * ly);
    float F = a * ly * ly + b * lx * lx + c * lx * ly;

    float al = alphas[p];
    float wr = colors[p * 3 + 0] * al;
    float wg = colors[p * 3 + 1] * al;
    float wb = colors[p * 3 + 2] * al;

    float4* q = g_pdata + p * 3;
    q[0] = make_float4(-b, -c, -E, -a);
    q[1] = make_float4(-D, 1.0f - F, wr, wg);
    q[2] = make_float4(wb, 0.0f, 0.0f, 0.0f);
}

// One warp per row: ordered compaction of active points (ballot + popc),
// preserving original point order so accumulation is bitwise-stable.
__global__ void build_lists_kernel(int H, int P)
{
    const int row  = blockIdx.x;
    const int lane = threadIdx.x;
    const float y  = -1.0f + (float)row * (2.0f / (float)(H - 1));

    int base = 0;
    for (int p0 = 0; p0 < P; p0 += 32) {
        int p = p0 + lane;
        bool act = false;
        float nb = 0.f, ng = 0.f, h1 = 0.f, wr = 0.f, wg = 0.f, wb = 0.f;
        if (p < P) {
            float4 q0 = g_pdata[p * 3 + 0];
            float4 q1 = g_pdata[p * 3 + 1];
            float4 q2 = g_pdata[p * 3 + 2];
            nb = q0.x;
            ng = fmaf(y, q0.y, q0.z);                    // nc*y + nE
            h1 = fmaf(y, fmaf(y, q0.w, q1.x), q1.y);     // (na*y+nD)*y + F1
            wr = q1.z; wg = q1.w; wb = q2.x;
            float peak = h1 - (ng * ng) / (4.0f * nb);   // nb < 0
            act = (peak > 0.0f);
        }
        unsigned m = __ballot_sync(0xffffffffu, act);
        int pos = base + __popc(m & ((1u << lane) - 1u));
        if (act && pos < ROWCAP) {
            float4* r = g_rowlist + ((size_t)row * ROWCAP + pos) * 3;
            r[0] = make_float4(nb, nb, ng, ng);
            r[1] = make_float4(h1, h1, wr, wr);
            r[2] = make_float4(wg, wg, wb, wb);
        }
        base += __popc(m);
    }
    if (lane == 0) g_rowcount[row] = (base < ROWCAP) ? base : ROWCAP;
}

#define TPB   128     // one block == one canvas row
#define NPAIR 2       // pixel pairs per thread -> 4 px/thread, 512 px/block

__global__ __launch_bounds__(TPB)
void render_kernel(float* __restrict__ out, int H, int W, float ratio)
{
    extern __shared__ float4 s4[];   // 3 * count float4 (cap: 3 * P)

    const int row   = blockIdx.x;
    const int count = g_rowcount[row];

    const float4* src = g_rowlist + (size_t)row * ROWCAP * 3;
    for (int i = threadIdx.x; i < count * 3; i += TPB) s4[i] = src[i];
    __syncthreads();

    const float dx = 2.0f * ratio / (float)(W - 1);

    u64 x2[NPAIR];
#pragma unroll
    for (int k = 0; k < NPAIR; k++) {
        int px = (threadIdx.x + k * TPB) * 2;
        x2[k] = pack2(-ratio + (float)px * dx, -ratio + (float)(px + 1) * dx);
    }

    u64 ar[NPAIR], ag[NPAIR], ab[NPAIR];
    const u64 z2 = pack2(0.0f, 0.0f);
#pragma unroll
    for (int k = 0; k < NPAIR; k++) { ar[k] = z2; ag[k] = z2; ab[k] = z2; }

    for (int p = 0; p < count; p++) {
        const float4 r0 = s4[p * 3 + 0];
        const float4 r1 = s4[p * 3 + 1];
        const float4 r2 = s4[p * 3 + 2];

        const u64 nb2 = pack2(r0.x, r0.y);
        const u64 ng2 = pack2(r0.z, r0.w);
        const u64 h12 = pack2(r1.x, r1.y);
        const u64 wr2 = pack2(r1.z, r1.w);
        const u64 wg2 = pack2(r2.x, r2.y);
        const u64 wb2 = pack2(r2.z, r2.w);

#pragma unroll
        for (int k = 0; k < NPAIR; k++) {
            u64 t = ffma2(x2[k], nb2, ng2);
            u64 w = ffma2(x2[k], t, h12);
            float2 wf = unpack2(w);
            u64 m = pack2(fmaxf(wf.x, 0.0f), fmaxf(wf.y, 0.0f));
            ar[k] = ffma2(m, wr2, ar[k]);
            ag[k] = ffma2(m, wg2, ag[k]);
            ab[k] = ffma2(m, wb2, ab[k]);
        }
    }

    // sigmoid(4*canvas) epilogue + store (2 pixels = 6 contiguous floats)
#pragma unroll
    for (int k = 0; k < NPAIR; k++) {
        int px = (threadIdx.x + k * TPB) * 2;
        if (px + 1 < W) {
            float2 r = unpack2(ar[k]);
            float2 g = unpack2(ag[k]);
            float2 b = unpack2(ab[k]);
            float* o = out + ((size_t)row * W + px) * 3;
            o[0] = 1.0f / (1.0f + __expf(-4.0f * r.x));
            o[1] = 1.0f / (1.0f + __expf(-4.0f * g.x));
            o[2] = 1.0f / (1.0f + __expf(-4.0f * b.x));
            o[3] = 1.0f / (1.0f + __expf(-4.0f * r.y));
            o[4] = 1.0f / (1.0f + __expf(-4.0f * g.y));
            o[5] = 1.0f / (1.0f + __expf(-4.0f * b.y));
        }
    }
}

extern "C" void kernel_launch(void* const* d_in, const int* in_sizes, int n_in,
                              void* d_out, int out_size)
{
    const float* loc    = (const float*)d_in[2];
    const float* moff   = (const float*)d_in[3];
    const float* msfo   = (const float*)d_in[4];
    const float* colors = (const float*)d_in[5];
    const float* alphas = (const float*)d_in[6];
    float* out = (float*)d_out;

    int P = in_sizes[2] / 2;             // locations has P*2 elements
    int HW = out_size / 3;               // output is H*W*3
    int H = (int)(sqrt((double)HW) + 0.5);
    int W = HW / H;
    float ratio = (float)W / (float)H;

    prep_kernel<<<(P + 127) / 128, 128>>>(loc, moff, msfo, colors, alphas, P);
    build_lists_kernel<<<H, 32>>>(H, P);

    int cap = (P < ROWCAP) ? P : ROWCAP;
    size_t smem = (size_t)cap * 3 * sizeof(float4);   // 24 KB for P=512
    render_kernel<<<H, TPB, smem>>>(out, H, W, ratio);
}

// round 4
// speedup vs baseline: 3.8775x; 1.6800x over previous
#include <cuda_runtime.h>
#include <math.h>

typedef unsigned long long u64;

__device__ __forceinline__ u64 ffma2(u64 a, u64 b, u64 c) {
    u64 d;
    asm("fma.rn.f32x2 %0, %1, %2, %3;" : "=l"(d) : "l"(a), "l"(b), "l"(c));
    return d;
}
__device__ __forceinline__ u64 pack2(float lo, float hi) {
    u64 d;
    asm("mov.b64 %0, {%1, %2};" : "=l"(d) : "f"(lo), "f"(hi));
    return d;
}
__device__ __forceinline__ float2 unpack2(u64 a) {
    float2 r;
    asm("mov.b64 {%0, %1}, %2;" : "=f"(r.x), "=f"(r.y) : "l"(a));
    return r;
}

// d(x,y) = a*y^2 + b*x^2 + c*x*y + D*y + E*x + F ; m = max(1-d, 0)
// per-(row,point): quadratic in x:  nb*x^2 + ng*x + h1,  nb=-b<0
//   ng = nc*y + nE,  h1 = (na*y + nD)*y + F1
// row-active test (no div):  h1 - ng^2/(4nb) > 0  <=>  4*nb*h1 < ng^2

#define TPB   128     // one block == one canvas row (4 warps)
#define NPAIR 2       // pixel pairs per thread -> 4 px/thread, 512 px/block

__global__ __launch_bounds__(TPB)
void fused_kernel(const float* __restrict__ loc,
                  const float* __restrict__ moff,
                  const float* __restrict__ msfo,
                  const float* __restrict__ colors,
                  const float* __restrict__ alphas,
                  float* __restrict__ out,
                  int H, int W, int P, float ratio)
{
    extern __shared__ float4 s4[];   // 3 * P float4 (compacted active list)
    __shared__ int s_cnt;
    if (threadIdx.x == 0) s_cnt = 0;
    __syncthreads();

    const int row = blockIdx.x;
    const float y = -1.0f + (float)row * (2.0f / (float)(H - 1));
    const float sP = 0.5f * sqrtf((float)P);
    const int lane = threadIdx.x & 31;

    // Phase 1: per-point prep (recomputed per block) + row cull + compaction
    for (int p0 = 0; p0 < P; p0 += TPB) {
        const int p = p0 + threadIdx.x;
        const bool inb = (p < P);

        float nb = -1.f, ng = 0.f, h1 = -1.f;
        bool act = false;
        if (inb) {
            float scale = sP * __expf(msfo[p]);
            float4 m4 = ((const float4*)moff)[p];
            float T00 = m4.x + scale, T01 = m4.y;
            float T10 = m4.z,         T11 = m4.w + scale;

            float a = T00 * T00 + T01 * T01;
            float b = T10 * T10 + T11 * T11;
            float c = 2.0f * (T00 * T10 + T01 * T11);

            float2 l2 = ((const float2*)loc)[p];
            float ly = l2.x, lx = l2.y;

            float D = -(2.0f * a * ly + c * lx);
            float E = -(2.0f * b * lx + c * ly);
            float F = a * ly * ly + b * lx * lx + c * lx * ly;

            nb = -b;
            ng = fmaf(y, -c, -E);                               // nc*y + nE
            h1 = fmaf(y, fmaf(y, -a, -D), 1.0f - F);            // (na*y+nD)*y + F1
            act = (4.0f * nb * h1 < ng * ng);
        }

        unsigned msk = __ballot_sync(0xffffffffu, act);
        int pos = 0;
        if (msk) {
            int leader = __ffs(msk) - 1;
            int base = 0;
            if (lane == leader) base = atomicAdd(&s_cnt, __popc(msk));
            base = __shfl_sync(0xffffffffu, base, leader);
            pos = base + __popc(msk & ((1u << lane) - 1u));
        }
        if (act) {
            float al = alphas[p];
            float wr = colors[p * 3 + 0] * al;
            float wg = colors[p * 3 + 1] * al;
            float wb = colors[p * 3 + 2] * al;
            s4[pos * 3 + 0] = make_float4(nb, nb, ng, ng);
            s4[pos * 3 + 1] = make_float4(h1, h1, wr, wr);
            s4[pos * 3 + 2] = make_float4(wg, wg, wb, wb);
        }
    }
    __syncthreads();
    const int count = s_cnt;

    // Phase 2: render 512 pixels of this row over the compacted list
    const float dx = 2.0f * ratio / (float)(W - 1);

    u64 x2[NPAIR];
#pragma unroll
    for (int k = 0; k < NPAIR; k++) {
        int px = (threadIdx.x + k * TPB) * 2;
        x2[k] = pack2(-ratio + (float)px * dx, -ratio + (float)(px + 1) * dx);
    }

    u64 ar[NPAIR], ag[NPAIR], ab[NPAIR];
    const u64 z2 = pack2(0.0f, 0.0f);
#pragma unroll
    for (int k = 0; k < NPAIR; k++) { ar[k] = z2; ag[k] = z2; ab[k] = z2; }

    for (int p = 0; p < count; p++) {
        const float4 r0 = s4[p * 3 + 0];
        const float4 r1 = s4[p * 3 + 1];
        const float4 r2 = s4[p * 3 + 2];

        const u64 nb2 = pack2(r0.x, r0.y);
        const u64 ng2 = pack2(r0.z, r0.w);
        const u64 h12 = pack2(r1.x, r1.y);
        const u64 wr2 = pack2(r1.z, r1.w);
        const u64 wg2 = pack2(r2.x, r2.y);
        const u64 wb2 = pack2(r2.z, r2.w);

#pragma unroll
        for (int k = 0; k < NPAIR; k++) {
            u64 t = ffma2(x2[k], nb2, ng2);
            u64 w = ffma2(x2[k], t, h12);
            float2 wf = unpack2(w);
            u64 m = pack2(fmaxf(wf.x, 0.0f), fmaxf(wf.y, 0.0f));
            ar[k] = ffma2(m, wr2, ar[k]);
            ag[k] = ffma2(m, wg2, ag[k]);
            ab[k] = ffma2(m, wb2, ab[k]);
        }
    }

    // sigmoid(4*canvas) epilogue + store (2 pixels = 6 contiguous floats)
#pragma unroll
    for (int k = 0; k < NPAIR; k++) {
        int px = (threadIdx.x + k * TPB) * 2;
        if (px + 1 < W) {
            float2 r = unpack2(ar[k]);
            float2 g = unpack2(ag[k]);
            float2 b = unpack2(ab[k]);
            float* o = out + ((size_t)row * W + px) * 3;
            o[0] = 1.0f / (1.0f + __expf(-4.0f * r.x));
            o[1] = 1.0f / (1.0f + __expf(-4.0f * g.x));
            o[2] = 1.0f / (1.0f + __expf(-4.0f * b.x));
            o[3] = 1.0f / (1.0f + __expf(-4.0f * r.y));
            o[4] = 1.0f / (1.0f + __expf(-4.0f * g.y));
            o[5] = 1.0f / (1.0f + __expf(-4.0f * b.y));
        }
    }
}

extern "C" void kernel_launch(void* const* d_in, const int* in_sizes, int n_in,
                              void* d_out, int out_size)
{
    const float* loc    = (const float*)d_in[2];
    const float* moff   = (const float*)d_in[3];
    const float* msfo   = (const float*)d_in[4];
    const float* colors = (const float*)d_in[5];
    const float* alphas = (const float*)d_in[6];
    float* out = (float*)d_out;

    int P = in_sizes[2] / 2;             // locations has P*2 elements
    int HW = out_size / 3;               // output is H*W*3
    int H = (int)(sqrt((double)HW) + 0.5);
    int W = HW / H;
    float ratio = (float)W / (float)H;

    size_t smem = (size_t)P * 3 * sizeof(float4);   // 24 KB for P=512
    fused_kernel<<<H, TPB, smem>>>(loc, moff, msfo, colors, alphas,
                                   out, H, W, P, ratio);
}

// round 5
// speedup vs baseline: 3.8872x; 1.0025x over previous
#include <cuda_runtime.h>
#include <math.h>

typedef unsigned long long u64;

__device__ __forceinline__ u64 ffma2(u64 a, u64 b, u64 c) {
    u64 d;
    asm("fma.rn.f32x2 %0, %1, %2, %3;" : "=l"(d) : "l"(a), "l"(b), "l"(c));
    return d;
}
__device__ __forceinline__ u64 pack2(float lo, float hi) {
    u64 d;
    asm("mov.b64 %0, {%1, %2};" : "=l"(d) : "f"(lo), "f"(hi));
    return d;
}
__device__ __forceinline__ float2 unpack2(u64 a) {
    float2 r;
    asm("mov.b64 {%0, %1}, %2;" : "=f"(r.x), "=f"(r.y) : "l"(a));
    return r;
}

// d(x,y) = a*y^2 + b*x^2 + c*x*y + D*y + E*x + F ; m = max(1-d, 0)
// per-(row,point): quadratic in x:  nb*x^2 + ng*x + h1,  nb=-b<0
//   ng = nc*y + nE,  h1 = (na*y + nD)*y + F1
// row-active test (no div):  h1 - ng^2/(4nb) > 0  <=>  4*nb*h1 < ng^2

#define TPB 256       // one block == one canvas row (8 warps), 2 px/thread

__global__ __launch_bounds__(TPB)
void fused_kernel(const float* __restrict__ loc,
                  const float* __restrict__ moff,
                  const float* __restrict__ msfo,
                  const float* __restrict__ colors,
                  const float* __restrict__ alphas,
                  float* __restrict__ out,
                  int H, int W, int P, float ratio)
{
    extern __shared__ float4 s4[];   // 3 * (P+1) float4 (compacted list + pad)
    __shared__ int s_cnt;
    if (threadIdx.x == 0) s_cnt = 0;
    __syncthreads();

    const int row = blockIdx.x;
    const float y = -1.0f + (float)row * (2.0f / (float)(H - 1));
    const float sP = 0.5f * sqrtf((float)P);
    const int lane = threadIdx.x & 31;

    // ---- Phase 1: per-point prep + row cull + block compaction ----
    for (int p0 = 0; p0 < P; p0 += TPB) {
        const int p = p0 + threadIdx.x;
        const bool inb = (p < P);

        float nb = -1.f, ng = 0.f, h1 = -1.f;
        float wr = 0.f, wg = 0.f, wb = 0.f;
        bool act = false;
        if (inb) {
            // issue ALL loads up front (independent; MLP hides L2 latency)
            float  ms = msfo[p];
            float4 m4 = ((const float4*)moff)[p];
            float2 l2 = ((const float2*)loc)[p];
            float  c0 = colors[p * 3 + 0];
            float  c1 = colors[p * 3 + 1];
            float  c2 = colors[p * 3 + 2];
            float  al = alphas[p];

            float scale = sP * __expf(ms);
            float T00 = m4.x + scale, T01 = m4.y;
            float T10 = m4.z,         T11 = m4.w + scale;

            float a = T00 * T00 + T01 * T01;
            float b = T10 * T10 + T11 * T11;
            float c = 2.0f * (T00 * T10 + T01 * T11);

            float ly = l2.x, lx = l2.y;
            float D = -(2.0f * a * ly + c * lx);
            float E = -(2.0f * b * lx + c * ly);
            float F = a * ly * ly + b * lx * lx + c * lx * ly;

            nb = -b;
            ng = fmaf(y, -c, -E);                        // nc*y + nE
            h1 = fmaf(y, fmaf(y, -a, -D), 1.0f - F);     // (na*y+nD)*y + F1
            act = (4.0f * nb * h1 < ng * ng);
            wr = c0 * al; wg = c1 * al; wb = c2 * al;
        }

        unsigned msk = __ballot_sync(0xffffffffu, act);
        if (msk) {
            int leader = __ffs(msk) - 1;
            int base = 0;
            if (lane == leader) base = atomicAdd(&s_cnt, __popc(msk));
            base = __shfl_sync(0xffffffffu, base, leader);
            int pos = base + __popc(msk & ((1u << lane) - 1u));
            if (act) {
                s4[pos * 3 + 0] = make_float4(nb, nb, ng, ng);
                s4[pos * 3 + 1] = make_float4(h1, h1, wr, wr);
                s4[pos * 3 + 2] = make_float4(wg, wg, wb, wb);
            }
        }
    }
    __syncthreads();
    const int count = s_cnt;
    // padding record: m forced to 0 (h1=-1) and zero weights -> contributes 0
    if (threadIdx.x == 0) {
        s4[count * 3 + 0] = make_float4(0.f, 0.f, 0.f, 0.f);
        s4[count * 3 + 1] = make_float4(-1.f, -1.f, 0.f, 0.f);
        s4[count * 3 + 2] = make_float4(0.f, 0.f, 0.f, 0.f);
    }
    __syncthreads();

    // ---- Phase 2: render 2 pixels/thread over compacted list ----
    const float dx = 2.0f * ratio / (float)(W - 1);
    const int px = threadIdx.x * 2;
    const u64 x2 = pack2(-ratio + (float)px * dx, -ratio + (float)(px + 1) * dx);

    u64 ar = pack2(0.f, 0.f), ag = ar, ab = ar;

    // depth-1 software pipeline (pad record makes prefetch branch-free)
    float4 r0 = s4[0], r1 = s4[1], r2 = s4[2];
    for (int p = 0; p < count; p++) {
        float4 n0 = s4[(p + 1) * 3 + 0];
        float4 n1 = s4[(p + 1) * 3 + 1];
        float4 n2 = s4[(p + 1) * 3 + 2];

        const u64 nb2 = pack2(r0.x, r0.y);
        const u64 ng2 = pack2(r0.z, r0.w);
        const u64 h12 = pack2(r1.x, r1.y);
        const u64 wr2 = pack2(r1.z, r1.w);
        const u64 wg2 = pack2(r2.x, r2.y);
        const u64 wb2 = pack2(r2.z, r2.w);

        u64 t = ffma2(x2, nb2, ng2);
        u64 w = ffma2(x2, t, h12);
        float2 wf = unpack2(w);
        u64 m = pack2(fmaxf(wf.x, 0.0f), fmaxf(wf.y, 0.0f));
        ar = ffma2(m, wr2, ar);
        ag = ffma2(m, wg2, ag);
        ab = ffma2(m, wb2, ab);

        r0 = n0; r1 = n1; r2 = n2;
    }

    // sigmoid(4*canvas) epilogue + store (2 pixels = 6 contiguous floats)
    if (px + 1 < W) {
        float2 r = unpack2(ar);
        float2 g = unpack2(ag);
        float2 b = unpack2(ab);
        float* o = out + ((size_t)row * W + px) * 3;
        o[0] = 1.0f / (1.0f + __expf(-4.0f * r.x));
        o[1] = 1.0f / (1.0f + __expf(-4.0f * g.x));
        o[2] = 1.0f / (1.0f + __expf(-4.0f * b.x));
        o[3] = 1.0f / (1.0f + __expf(-4.0f * r.y));
        o[4] = 1.0f / (1.0f + __expf(-4.0f * g.y));
        o[5] = 1.0f / (1.0f + __expf(-4.0f * b.y));
    }
}

extern "C" void kernel_launch(void* const* d_in, const int* in_sizes, int n_in,
                              void* d_out, int out_size)
{
    const float* loc    = (const float*)d_in[2];
    const float* moff   = (const float*)d_in[3];
    const float* msfo   = (const float*)d_in[4];
    const float* colors = (const float*)d_in[5];
    const float* alphas = (const float*)d_in[6];
    float* out = (float*)d_out;

    int P = in_sizes[2] / 2;             // locations has P*2 elements
    int HW = out_size / 3;               // output is H*W*3
    int H = (int)(sqrt((double)HW) + 0.5);
    int W = HW / H;
    float ratio = (float)W / (float)H;

    size_t smem = ((size_t)P + 1) * 3 * sizeof(float4);   // ~24.6 KB for P=512
    fused_kernel<<<H, TPB, smem>>>(loc, moff, msfo, colors, alphas,
                                   out, H, W, P, ratio);
}

// round 6
// speedup vs baseline: 3.9566x; 1.0179x over previous
#include <cuda_runtime.h>
#include <math.h>

// d(x,y) = a*dy^2 + b*dx^2 + c*dy*dx  (dy=y-ly, dx=x-lx); m = max(1-d, 0)
// expanded:   d = a y^2 + b x^2 + c x y + D y + E x + F
// per-point record (y-independent): nb=-b, nc=-c, nE=-E, na=-a, nD=-D, F1=1-F, w*=color*alpha
// per-(row,point) in render: ng = nc*y + nE ; h1 = (na*y + nD)*y + F1
// tile cull: ellipse d<1 has bbox half-extents sqrt(b/det), sqrt(a/det) around loc,
//   det = a*b - c^2/4.  Overlap test (sqrt/div-free, conservative at det<=0):
//   max(|ly-yc|-hy,0)^2 * det <= b   AND   max(|lx-xc|-hx,0)^2 * det <= a

#define TW  64        // tile width  (pixels)
#define TH  8         // tile height (rows)
#define TPB 256       // 8 warps; warp w renders row w of the tile; 2 px/thread

__global__ __launch_bounds__(TPB)
void fused_kernel(const float* __restrict__ loc,
                  const float* __restrict__ moff,
                  const float* __restrict__ msfo,
                  const float* __restrict__ colors,
                  const float* __restrict__ alphas,
                  float* __restrict__ out,
                  int H, int W, int P, float ratio)
{
    extern __shared__ float smem[];
    // staging: msfo[P] | moff[4P] | loc[2P] | colors[3P] | alphas[P]  (11P floats)
    float* s_msfo = smem;
    float* s_moff = s_msfo + P;
    float* s_loc  = s_moff + 4 * P;
    float* s_col  = s_loc  + 2 * P;
    float* s_alp  = s_col  + 3 * P;
    const int list_off = ((11 * P + 3) & ~3);       // 16B-align the list
    float4* s_list = (float4*)(smem + list_off);    // 3 float4 per active point
    __shared__ int s_cnt;

    const int tid = threadIdx.x;
    if (tid == 0) s_cnt = 0;

    // ---- Stage all inputs into shared memory (coalesced, independent LDGs) ----
    for (int i = tid; i < P; i += TPB)     { s_msfo[i] = msfo[i]; s_alp[i] = alphas[i]; }
    for (int i = tid; i < 4 * P; i += TPB)   s_moff[i] = moff[i];
    for (int i = tid; i < 2 * P; i += TPB)   s_loc[i]  = loc[i];
    for (int i = tid; i < 3 * P; i += TPB)   s_col[i]  = colors[i];
    __syncthreads();

    // ---- Tile geometry ----
    const float dyp = 2.0f / (float)(H - 1);
    const float dxp = 2.0f * ratio / (float)(W - 1);
    const int tx = blockIdx.x, ty = blockIdx.y;

    const float y0 = -1.0f   + (float)(ty * TH) * dyp;
    const float x0 = -ratio  + (float)(tx * TW) * dxp;
    const float hy = 0.5f * (float)(TH - 1) * dyp;
    const float hx = 0.5f * (float)(TW - 1) * dxp;
    const float yc = y0 + hy;
    const float xc = x0 + hx;

    const float sP = 0.5f * sqrtf((float)P);
    const int lane = tid & 31;

    // ---- Phase 1: per-point prep + tile cull + compaction ----
    for (int p0 = 0; p0 < P; p0 += TPB) {
        const int p = p0 + tid;
        bool act = false;
        float nb = 0.f, nc = 0.f, nE = 0.f, na = 0.f, nD = 0.f, F1 = 0.f;
        float wr = 0.f, wg = 0.f, wb = 0.f;
        if (p < P) {
            float scale = sP * __expf(s_msfo[p]);
            float T00 = s_moff[4 * p + 0] + scale;
            float T01 = s_moff[4 * p + 1];
            float T10 = s_moff[4 * p + 2];
            float T11 = s_moff[4 * p + 3] + scale;

            float a = T00 * T00 + T01 * T01;
            float b = T10 * T10 + T11 * T11;
            float c = 2.0f * (T00 * T10 + T01 * T11);

            float ly = s_loc[2 * p + 0];
            float lx = s_loc[2 * p + 1];

            float det = fmaf(a, b, -0.25f * c * c);
            float tdy = fmaxf(fabsf(ly - yc) - hy, 0.0f);
            float tdx = fmaxf(fabsf(lx - xc) - hx, 0.0f);
            act = (tdy * tdy * det <= b) && (tdx * tdx * det <= a);

            if (act) {
                float D = -(2.0f * a * ly + c * lx);
                float E = -(2.0f * b * lx + c * ly);
                float F = a * ly * ly + b * lx * lx + c * lx * ly;
                nb = -b; nc = -c; nE = -E; na = -a; nD = -D; F1 = 1.0f - F;
                float al = s_alp[p];
                wr = s_col[3 * p + 0] * al;
                wg = s_col[3 * p + 1] * al;
                wb = s_col[3 * p + 2] * al;
            }
        }
        unsigned msk = __ballot_sync(0xffffffffu, act);
        if (msk) {
            int leader = __ffs(msk) - 1;
            int base = 0;
            if (lane == leader) base = atomicAdd(&s_cnt, __popc(msk));
            base = __shfl_sync(0xffffffffu, base, leader);
            int pos = base + __popc(msk & ((1u << lane) - 1u));
            if (act) {
                s_list[pos * 3 + 0] = make_float4(nb, nc, nE, na);
                s_list[pos * 3 + 1] = make_float4(nD, F1, wr, wg);
                s_list[pos * 3 + 2] = make_float4(wb, 0.f, 0.f, 0.f);
            }
        }
    }
    __syncthreads();
    const int count = s_cnt;

    // ---- Phase 2: render 2 adjacent pixels/thread; warp w == tile row w ----
    const int rowi = tid >> 5;                 // 0..TH-1 (uniform per warp)
    const int gy = ty * TH + rowi;
    const int gx = tx * TW + lane * 2;
    const float y  = -1.0f  + (float)gy * dyp;
    const float xa = -ratio + (float)gx * dxp;
    const float xb = xa + dxp;

    float ar0 = 0.f, ag0 = 0.f, ab0 = 0.f;
    float ar1 = 0.f, ag1 = 0.f, ab1 = 0.f;

    for (int p = 0; p < count; p++) {
        const float4 r0 = s_list[p * 3 + 0];
        const float4 r1 = s_list[p * 3 + 1];
        const float4 r2 = s_list[p * 3 + 2];

        float ng = fmaf(y, r0.y, r0.z);                      // nc*y + nE
        float h1 = fmaf(y, fmaf(y, r0.w, r1.x), r1.y);       // (na*y+nD)*y + F1

        float w0 = fmaf(xa, fmaf(xa, r0.x, ng), h1);
        float w1 = fmaf(xb, fmaf(xb, r0.x, ng), h1);
        float m0 = fmaxf(w0, 0.0f);
        float m1 = fmaxf(w1, 0.0f);

        ar0 = fmaf(m0, r1.z, ar0);  ar1 = fmaf(m1, r1.z, ar1);
        ag0 = fmaf(m0, r1.w, ag0);  ag1 = fmaf(m1, r1.w, ag1);
        ab0 = fmaf(m0, r2.x, ab0);  ab1 = fmaf(m1, r2.x, ab1);
    }

    // ---- sigmoid(4*canvas) epilogue + store (2 px = 6 contiguous floats) ----
    if (gy < H && gx + 1 < W) {
        float* o = out + ((size_t)gy * W + gx) * 3;
        o[0] = 1.0f / (1.0f + __expf(-4.0f * ar0));
        o[1] = 1.0f / (1.0f + __expf(-4.0f * ag0));
        o[2] = 1.0f / (1.0f + __expf(-4.0f * ab0));
        o[3] = 1.0f / (1.0f + __expf(-4.0f * ar1));
        o[4] = 1.0f / (1.0f + __expf(-4.0f * ag1));
        o[5] = 1.0f / (1.0f + __expf(-4.0f * ab1));
    }
}

extern "C" void kernel_launch(void* const* d_in, const int* in_sizes, int n_in,
                              void* d_out, int out_size)
{
    const float* loc    = (const float*)d_in[2];
    const float* moff   = (const float*)d_in[3];
    const float* msfo   = (const float*)d_in[4];
    const float* colors = (const float*)d_in[5];
    const float* alphas = (const float*)d_in[6];
    float* out = (float*)d_out;

    int P = in_sizes[2] / 2;             // locations has P*2 elements
    int HW = out_size / 3;               // output is H*W*3
    int H = (int)(sqrt((double)HW) + 0.5);
    int W = HW / H;
    float ratio = (float)W / (float)H;

    // smem: 11P floats staging (aligned to 4) + 3P float4 list
    int list_off = ((11 * P + 3) & ~3);
    size_t smem = (size_t)list_off * sizeof(float) + (size_t)P * 3 * sizeof(float4);

    cudaFuncSetAttribute(fused_kernel,
                         cudaFuncAttributeMaxDynamicSharedMemorySize, (int)smem);

    dim3 grid((W + TW - 1) / TW, (H + TH - 1) / TH);
    fused_kernel<<<grid, TPB, smem>>>(loc, moff, msfo, colors, alphas,
                                      out, H, W, P, ratio);
}

// round 7
// speedup vs baseline: 4.6299x; 1.1701x over previous
#include <cuda_runtime.h>
#include <math.h>

// d(x,y) = a*dy^2 + b*dx^2 + c*dy*dx  (dy=y-ly, dx=x-lx); m = max(1-d, 0)
// expanded: d = a y^2 + b x^2 + c x y + D y + E x + F
// record: A=(nb,nc,nE,na)  B=(nD,F1,wr,wg)  wb   with nb=-b etc., F1=1-F
// render per (row,pt): ng = nc*y + nE ; h1 = (na*y + nD)*y + F1
// tile cull (sqrt/div-free, conservative): det = ab - c^2/4
//   max(|ly-yc|-hy,0)^2 * det <= b  AND  max(|lx-xc|-hx,0)^2 * det <= a

#define TW  64        // tile width  (pixels)
#define TH  16        // tile height (rows)
#define TPB 512       // 16 warps; warp w renders tile row w; 2 px/thread

__global__ __launch_bounds__(TPB)
void fused_kernel(const float* __restrict__ loc,
                  const float* __restrict__ moff,
                  const float* __restrict__ msfo,
                  const float* __restrict__ colors,
                  const float* __restrict__ alphas,
                  float* __restrict__ out,
                  int H, int W, int P, float ratio)
{
    extern __shared__ float smem[];
    float4* s_A  = (float4*)smem;              // P float4
    float4* s_B  = s_A + P;                    // P float4
    float*  s_wb = (float*)(s_B + P);          // P floats
    __shared__ int s_cnt;

    const int tid  = threadIdx.x;
    const int lane = tid & 31;
    if (tid == 0) s_cnt = 0;
    __syncthreads();

    // ---- Tile geometry ----
    const float dyp = 2.0f / (float)(H - 1);
    const float dxp = 2.0f * ratio / (float)(W - 1);
    const int tx = blockIdx.x, ty = blockIdx.y;

    const float hy = 0.5f * (float)(TH - 1) * dyp;
    const float hx = 0.5f * (float)(TW - 1) * dxp;
    const float yc = -1.0f  + (float)(ty * TH) * dyp + hy;
    const float xc = -ratio + (float)(tx * TW) * dxp + hx;

    const float sP = 0.5f * sqrtf((float)P);

    // ---- Phase 1: prep + tile cull + compaction (direct global reads) ----
    for (int p0 = 0; p0 < P; p0 += TPB) {
        const int p = p0 + tid;
        bool act = false;
        float a = 0.f, b = 0.f, c = 0.f, ly = 0.f, lx = 0.f;
        if (p < P) {
            float  ms = __ldg(msfo + p);
            float4 m4 = __ldg((const float4*)moff + p);
            float2 l2 = __ldg((const float2*)loc + p);

            float scale = sP * __expf(ms);
            float T00 = m4.x + scale, T01 = m4.y;
            float T10 = m4.z,         T11 = m4.w + scale;

            a = T00 * T00 + T01 * T01;
            b = T10 * T10 + T11 * T11;
            c = 2.0f * (T00 * T10 + T01 * T11);
            ly = l2.x; lx = l2.y;

            float det = fmaf(a, b, -0.25f * c * c);
            float tdy = fmaxf(fabsf(ly - yc) - hy, 0.0f);
            float tdx = fmaxf(fabsf(lx - xc) - hx, 0.0f);
            act = (tdy * tdy * det <= b) && (tdx * tdx * det <= a);
        }
        unsigned msk = __ballot_sync(0xffffffffu, act);
        if (msk) {
            int leader = __ffs(msk) - 1;
            int base = 0;
            if (lane == leader) base = atomicAdd(&s_cnt, __popc(msk));
            base = __shfl_sync(0xffffffffu, base, leader);
            int pos = base + __popc(msk & ((1u << lane) - 1u));
            if (act) {
                float D = -(2.0f * a * ly + c * lx);
                float E = -(2.0f * b * lx + c * ly);
                float F = a * ly * ly + b * lx * lx + c * lx * ly;
                float al = __ldg(alphas + p);
                float wr = __ldg(colors + 3 * p + 0) * al;
                float wg = __ldg(colors + 3 * p + 1) * al;
                float wb = __ldg(colors + 3 * p + 2) * al;
                s_A[pos]  = make_float4(-b, -c, -E, -a);
                s_B[pos]  = make_float4(-D, 1.0f - F, wr, wg);
                s_wb[pos] = wb;
            }
        }
    }
    __syncthreads();
    const int count = s_cnt;

    // ---- Phase 2: render 2 adjacent px/thread; warp w == tile row w ----
    const int rowi = tid >> 5;                 // 0..TH-1 (uniform per warp)
    const int gy = ty * TH + rowi;
    const int gx = tx * TW + lane * 2;
    const float y  = -1.0f  + (float)gy * dyp;
    const float xa = -ratio + (float)gx * dxp;
    const float xb = xa + dxp;

    float ar0 = 0.f, ag0 = 0.f, ab0 = 0.f;
    float ar1 = 0.f, ag1 = 0.f, ab1 = 0.f;

    for (int p = 0; p < count; p++) {
        const float4 rA = s_A[p];
        const float4 rB = s_B[p];
        const float  wb = s_wb[p];

        float ng = fmaf(y, rA.y, rA.z);                      // nc*y + nE
        float h1 = fmaf(y, fmaf(y, rA.w, rB.x), rB.y);       // (na*y+nD)*y + F1

        float w0 = fmaf(xa, fmaf(xa, rA.x, ng), h1);
        float w1 = fmaf(xb, fmaf(xb, rA.x, ng), h1);
        float m0 = fmaxf(w0, 0.0f);
        float m1 = fmaxf(w1, 0.0f);

        ar0 = fmaf(m0, rB.z, ar0);  ar1 = fmaf(m1, rB.z, ar1);
        ag0 = fmaf(m0, rB.w, ag0);  ag1 = fmaf(m1, rB.w, ag1);
        ab0 = fmaf(m0, wb,  ab0);   ab1 = fmaf(m1, wb,  ab1);
    }

    // ---- sigmoid(4*canvas) epilogue + store (2 px = 6 contiguous floats) ----
    if (gy < H && gx + 1 < W) {
        float* o = out + ((size_t)gy * W + gx) * 3;
        o[0] = 1.0f / (1.0f + __expf(-4.0f * ar0));
        o[1] = 1.0f / (1.0f + __expf(-4.0f * ag0));
        o[2] = 1.0f / (1.0f + __expf(-4.0f * ab0));
        o[3] = 1.0f / (1.0f + __expf(-4.0f * ar1));
        o[4] = 1.0f / (1.0f + __expf(-4.0f * ag1));
        o[5] = 1.0f / (1.0f + __expf(-4.0f * ab1));
    }
}

extern "C" void kernel_launch(void* const* d_in, const int* in_sizes, int n_in,
                              void* d_out, int out_size)
{
    const float* loc    = (const float*)d_in[2];
    const float* moff   = (const float*)d_in[3];
    const float* msfo   = (const float*)d_in[4];
    const float* colors = (const float*)d_in[5];
    const float* alphas = (const float*)d_in[6];
    float* out = (float*)d_out;

    int P = in_sizes[2] / 2;             // locations has P*2 elements
    int HW = out_size / 3;               // output is H*W*3
    int H = (int)(sqrt((double)HW) + 0.5);
    int W = HW / H;
    float ratio = (float)W / (float)H;

    size_t smem = (size_t)P * (2 * sizeof(float4) + sizeof(float)); // 18 KB @P=512
    cudaFuncSetAttribute(fused_kernel,
                         cudaFuncAttributeMaxDynamicSharedMemorySize, (int)smem);

    dim3 grid((W + TW - 1) / TW, (H + TH - 1) / TH);
    fused_kernel<<<grid, TPB, smem>>>(loc, moff, msfo, colors, alphas,
                                      out, H, W, P, ratio);
}